// round 6
// baseline (speedup 1.0000x reference)
#include <cuda_runtime.h>
#include <cstdint>

// ---------------------------------------------------------------------------
// MoE top-2 projection: out[t] = sum_k w_k * (x[t] @ W[e_k]^T + b[e_k])
// x:[8192,1024] f32, W:[8,1024,1024], b:[8,1024], Wg:[8,1024], bg:[8]
// Route -> per-expert gathered GEMM with mma.sync tf32 (sm_100 baseline
// target: tcgen05 is sm_100a-only and this bench compiles for sm_100).
// ---------------------------------------------------------------------------

#define T_TOKENS 8192
#define DIM      1024
#define OUTD     1024
#define NEXP     8

// Scratch (allocation-free rule: __device__ globals)
__device__ float g_x_tf32[T_TOKENS * DIM];        // 32 MB
__device__ float g_w_tf32[NEXP * OUTD * DIM];     // 32 MB
__device__ int   g_cnt[NEXP];
__device__ int   g_tok[NEXP * T_TOKENS];
__device__ float g_wt [NEXP * T_TOKENS];

__device__ __forceinline__ float tf32_rn(float a) {
    uint32_t u;
    asm("cvt.rna.tf32.f32 %0, %1;" : "=r"(u) : "f"(a));
    return __uint_as_float(u);
}

// ---------------------------------------------------------------------------
// Kernel 1: zero d_out + counters, convert W -> tf32-rounded scratch.
// W floats = 8*1024*1024 = 8388608 = out floats -> one loop covers both.
// ---------------------------------------------------------------------------
__global__ void __launch_bounds__(256) prep_kernel(const float4* __restrict__ W,
                                                   float4* __restrict__ out4) {
    if (blockIdx.x == 0 && threadIdx.x < NEXP) g_cnt[threadIdx.x] = 0;
    int gid = blockIdx.x * blockDim.x + threadIdx.x;
    const int N4 = NEXP * OUTD * DIM / 4;  // 2097152
    float4* wo = reinterpret_cast<float4*>(g_w_tf32);
    float4 z = make_float4(0.f, 0.f, 0.f, 0.f);
    for (int j = gid; j < N4; j += gridDim.x * blockDim.x) {
        float4 v = W[j];
        v.x = tf32_rn(v.x); v.y = tf32_rn(v.y);
        v.z = tf32_rn(v.z); v.w = tf32_rn(v.w);
        wo[j] = v;
        out4[j] = z;
    }
}

// ---------------------------------------------------------------------------
// Kernel 2: gating (exact fp32), top-2 routing, and x -> tf32 scratch.
// 1 warp per token, 8 tokens per 256-thread CTA, Wg staged in SMEM.
// ---------------------------------------------------------------------------
__global__ void __launch_bounds__(256) gating_kernel(const float* __restrict__ x,
                                                     const float* __restrict__ wg,
                                                     const float* __restrict__ bg) {
    __shared__ float4 s_wg[NEXP * DIM / 4];  // 2048 float4 = 32 KB
    const int tid = threadIdx.x;
    const float4* wg4 = (const float4*)wg;
    for (int i = tid; i < NEXP * DIM / 4; i += 256) s_wg[i] = wg4[i];
    __syncthreads();

    const int lid = tid & 31;
    const int t = blockIdx.x * 8 + (tid >> 5);
    const float4* xr = (const float4*)(x + (size_t)t * DIM);
    float4* xo = (float4*)(g_x_tf32 + (size_t)t * DIM);

    float acc[NEXP];
#pragma unroll
    for (int e = 0; e < NEXP; e++) acc[e] = 0.f;

#pragma unroll
    for (int j = 0; j < 8; j++) {
        int c = lid + j * 32;
        float4 v = xr[c];
        float4 vt;
        vt.x = tf32_rn(v.x); vt.y = tf32_rn(v.y);
        vt.z = tf32_rn(v.z); vt.w = tf32_rn(v.w);
        xo[c] = vt;
#pragma unroll
        for (int e = 0; e < NEXP; e++) {
            float4 w = s_wg[e * 256 + c];
            acc[e] += v.x * w.x + v.y * w.y + v.z * w.z + v.w * w.w;
        }
    }
#pragma unroll
    for (int e = 0; e < NEXP; e++) {
#pragma unroll
        for (int o = 16; o > 0; o >>= 1)
            acc[e] += __shfl_xor_sync(0xFFFFFFFFu, acc[e], o);
    }

    if (lid == 0) {
        float l[NEXP];
#pragma unroll
        for (int e = 0; e < NEXP; e++) l[e] = acc[e] + bg[e];  // TEMP = 1
        int i0 = 0;
#pragma unroll
        for (int e = 1; e < NEXP; e++) if (l[e] > l[i0]) i0 = e;
        int i1 = -1;
#pragma unroll
        for (int e = 0; e < NEXP; e++) {
            if (e == i0) continue;
            if (i1 < 0 || l[e] > l[i1]) i1 = e;
        }
        float mx = l[0];
#pragma unroll
        for (int e = 1; e < NEXP; e++) mx = fmaxf(mx, l[e]);
        float s = 0.f;
#pragma unroll
        for (int e = 0; e < NEXP; e++) s += expf(l[e] - mx);
        float inv = 1.f / s;
        float w0 = expf(l[i0] - mx) * inv;
        float w1 = expf(l[i1] - mx) * inv;
        int p0 = atomicAdd(&g_cnt[i0], 1);
        g_tok[i0 * T_TOKENS + p0] = t; g_wt[i0 * T_TOKENS + p0] = w0;
        int p1 = atomicAdd(&g_cnt[i1], 1);
        g_tok[i1 * T_TOKENS + p1] = t; g_wt[i1 * T_TOKENS + p1] = w1;
    }
}

// ---------------------------------------------------------------------------
// sm_100-portable helpers
// ---------------------------------------------------------------------------
__device__ __forceinline__ uint32_t smem_u32(const void* p) {
    uint32_t a;
    asm("{ .reg .u64 t; cvta.to.shared.u64 t, %1; cvt.u32.u64 %0, t; }"
        : "=r"(a) : "l"(p));
    return a;
}
__device__ __forceinline__ void cp16(uint32_t dst, const void* src, uint32_t sz) {
    asm volatile("cp.async.cg.shared.global [%0], [%1], 16, %2;"
                 :: "r"(dst), "l"(src), "r"(sz) : "memory");
}
__device__ __forceinline__ void ldm_x4(uint32_t* r, uint32_t addr) {
    asm volatile("ldmatrix.sync.aligned.m8n8.x4.shared.b16 {%0,%1,%2,%3}, [%4];"
                 : "=r"(r[0]), "=r"(r[1]), "=r"(r[2]), "=r"(r[3]) : "r"(addr));
}
__device__ __forceinline__ void mma_tf32(float* c, const uint32_t* a,
                                         uint32_t b0, uint32_t b1) {
    asm volatile(
        "mma.sync.aligned.m16n8k8.row.col.f32.tf32.tf32.f32 "
        "{%0,%1,%2,%3}, {%4,%5,%6,%7}, {%8,%9}, {%0,%1,%2,%3};"
        : "+f"(c[0]), "+f"(c[1]), "+f"(c[2]), "+f"(c[3])
        : "r"(a[0]), "r"(a[1]), "r"(a[2]), "r"(a[3]), "r"(b0), "r"(b1));
}
__device__ __forceinline__ void red2(float* p, float a, float b) {
    asm volatile("red.relaxed.gpu.global.add.v2.f32 [%0], {%1, %2};"
                 :: "l"(p), "f"(a), "f"(b) : "memory");
}

// ---------------------------------------------------------------------------
// Kernel 3: routed GEMM. grid = (8 N-tiles, 64 M-tiles, 8 experts).
// 128x128x1024 per CTA; BK=32; 8 warps in 2x4 -> warp tile 64x32.
// SMEM: sA/sB stored k-contiguous with 144B row pitch (conflict-free
// ldmatrix); non-trans ldmatrix.x4 on f32-as-b16 yields exact tf32
// m16n8k8 A and B fragments. 2-stage cp.async pipeline.
// SMEM floats: sA 2*4608, sB 2*4608, tok 128, wt 128 -> 74752 B.
// ---------------------------------------------------------------------------
#define PITCH_F 36        // floats per smem row (144 B)
#define STAGE_F 4608      // 128 * 36 floats per stage
#define STAGE_B 18432     // bytes per stage

__global__ void __launch_bounds__(256, 2)
moe_gemm_kernel(const float* __restrict__ bias, float* __restrict__ out) {
    extern __shared__ float smem[];
    const int e  = blockIdx.z;
    const int mt = blockIdx.y;
    const int nt = blockIdx.x;
    const int cnt = g_cnt[e];
    if (mt * 128 >= cnt) return;

    const int tid  = threadIdx.x;
    const int wid  = tid >> 5;
    const int lane = tid & 31;
    const int wm   = wid & 1;   // 2 m-blocks of 64
    const int wn   = wid >> 1;  // 4 n-blocks of 32

    float* sA   = smem;
    float* sB   = smem + 2 * STAGE_F;
    int*   sTok = (int*)(smem + 4 * STAGE_F);
    float* sWt  = smem + 4 * STAGE_F + 128;

    if (tid < 128) {
        int idx = mt * 128 + tid;
        int tok = -1; float w = 0.f;
        if (idx < cnt) { tok = g_tok[e * T_TOKENS + idx]; w = g_wt[e * T_TOKENS + idx]; }
        sTok[tid] = tok; sWt[tid] = w;
    }
    __syncthreads();

    // --- per-thread global/smem slots: f = tid + i*256 covers 1024 float4 ---
    const float* aSrc[4];
    const float* bSrc[4];
    uint32_t     aSz[4];
    uint32_t     dstOff[4];
    const float* wrow = g_w_tf32 + ((size_t)(e * OUTD + nt * 128)) * DIM;
#pragma unroll
    for (int i = 0; i < 4; i++) {
        int f = tid + i * 256;
        int r = f >> 3, q = f & 7;       // r = tile row, q = float4 within 32 floats
        int tok = sTok[r];
        aSrc[i] = (tok >= 0 ? g_x_tf32 + (size_t)tok * DIM : g_x_tf32) + q * 4;
        aSz[i]  = (tok >= 0) ? 16u : 0u; // zfill padding rows
        bSrc[i] = wrow + (size_t)r * DIM + q * 4;
        dstOff[i] = (uint32_t)(r * (PITCH_F * 4) + q * 16);
    }

    const uint32_t aBase = smem_u32(sA);
    const uint32_t bBase = smem_u32(sB);

    auto prefetch = [&](int s) {
        uint32_t st = (uint32_t)(s & 1) * STAGE_B;
        int ko = s * 32;  // float offset along K
#pragma unroll
        for (int i = 0; i < 4; i++) cp16(aBase + st + dstOff[i], aSrc[i] + ko, aSz[i]);
#pragma unroll
        for (int i = 0; i < 4; i++) cp16(bBase + st + dstOff[i], bSrc[i] + ko, 16u);
    };

    prefetch(0);
    asm volatile("cp.async.commit_group;" ::: "memory");
    prefetch(1);
    asm volatile("cp.async.commit_group;" ::: "memory");

    // ldmatrix fragment addresses (bytes)
    // A: row = wm*64 + mf*16 + (lane&15); kbyte = kk*32 + (lane>>4)*16
    // B: row = wn*32 + pr*16 + (lane>>4)*8 + (lane&7); kbyte = kk*32 + ((lane>>3)&1)*16
    const uint32_t aAddr0 = aBase + (uint32_t)((wm * 64 + (lane & 15)) * (PITCH_F * 4))
                                  + (uint32_t)((lane >> 4) * 16);
    const uint32_t bAddr0 = bBase + (uint32_t)((wn * 32 + ((lane >> 4) << 3) + (lane & 7)) * (PITCH_F * 4))
                                  + (uint32_t)(((lane >> 3) & 1) * 16);

    float c[4][4][4];
#pragma unroll
    for (int mf = 0; mf < 4; mf++)
#pragma unroll
        for (int nf = 0; nf < 4; nf++)
#pragma unroll
            for (int j = 0; j < 4; j++) c[mf][nf][j] = 0.f;

    for (int s = 0; s < 32; s++) {
        asm volatile("cp.async.wait_group 1;" ::: "memory");
        __syncthreads();
        const uint32_t sa = aAddr0 + (uint32_t)(s & 1) * STAGE_B;
        const uint32_t sb = bAddr0 + (uint32_t)(s & 1) * STAGE_B;
#pragma unroll
        for (int kk = 0; kk < 4; kk++) {
            uint32_t a[4][4];
#pragma unroll
            for (int mf = 0; mf < 4; mf++)
                ldm_x4(a[mf], sa + (uint32_t)(mf * 16 * PITCH_F * 4) + (uint32_t)(kk * 32));
            uint32_t b[2][4];
#pragma unroll
            for (int pr = 0; pr < 2; pr++)
                ldm_x4(b[pr], sb + (uint32_t)(pr * 16 * PITCH_F * 4) + (uint32_t)(kk * 32));
#pragma unroll
            for (int mf = 0; mf < 4; mf++)
#pragma unroll
                for (int nf = 0; nf < 4; nf++)
                    mma_tf32(c[mf][nf], a[mf],
                             b[nf >> 1][(nf & 1) * 2], b[nf >> 1][(nf & 1) * 2 + 1]);
        }
        __syncthreads();
        if (s + 2 < 32) prefetch(s + 2);
        asm volatile("cp.async.commit_group;" ::: "memory");
    }

    // --- epilogue: bias + gate-weight scale + vectorized global reduction ---
    const int nbase = nt * 128;
    const float* bptr = bias + e * OUTD + nbase;
#pragma unroll
    for (int mf = 0; mf < 4; mf++) {
        int m0 = wm * 64 + mf * 16 + (lane >> 2);
        int m1 = m0 + 8;
        int t0 = sTok[m0], t1 = sTok[m1];
        float w0 = sWt[m0], w1 = sWt[m1];
#pragma unroll
        for (int nf = 0; nf < 4; nf++) {
            int col = wn * 32 + nf * 8 + 2 * (lane & 3);
            float2 bb = *(const float2*)(bptr + col);
            if (t0 >= 0) {
                red2(out + (size_t)t0 * OUTD + nbase + col,
                     w0 * (c[mf][nf][0] + bb.x), w0 * (c[mf][nf][1] + bb.y));
            }
            if (t1 >= 0) {
                red2(out + (size_t)t1 * OUTD + nbase + col,
                     w1 * (c[mf][nf][2] + bb.x), w1 * (c[mf][nf][3] + bb.y));
            }
        }
    }
}

// ---------------------------------------------------------------------------
extern "C" void kernel_launch(void* const* d_in, const int* in_sizes, int n_in,
                              void* d_out, int out_size) {
    const float* x  = (const float*)d_in[0];   // [4,2048,1024]
    const float* W  = (const float*)d_in[1];   // [8,1024,1024]
    const float* b  = (const float*)d_in[2];   // [8,1024]
    const float* Wg = (const float*)d_in[3];   // [8,1024]
    const float* bg = (const float*)d_in[4];   // [8]
    float* out = (float*)d_out;                // [4,2048,1024] f32

    static bool attr_set = false;
    if (!attr_set) {
        cudaFuncSetAttribute(moe_gemm_kernel,
                             cudaFuncAttributeMaxDynamicSharedMemorySize, 74752);
        attr_set = true;
    }

    prep_kernel<<<2048, 256>>>((const float4*)W, (float4*)out);
    gating_kernel<<<1024, 256>>>(x, Wg, bg);
    dim3 grid(8, 64, 8);
    moe_gemm_kernel<<<grid, 256, 74752>>>(b, out);
}

// round 7
// speedup vs baseline: 1.5295x; 1.5295x over previous
#include <cuda_runtime.h>
#include <cuda_fp16.h>
#include <cstdint>

// ---------------------------------------------------------------------------
// MoE top-2 projection: out[t] = sum_k w_k * (x[t] @ W[e_k]^T + b[e_k])
// x:[8192,1024] f32, W:[8,1024,1024], b:[8,1024], Wg:[8,1024], bg:[8]
// Route -> per-expert gathered GEMM with mma.sync fp16 (f32 accumulate).
// fp16 RNE carries the same 10-bit mantissa error as tf32-RNA (rel_err ~3e-4)
// but the legacy mma pipe runs fp16 at 2x the tf32 rate.
// ---------------------------------------------------------------------------

#define T_TOKENS 8192
#define DIM      1024
#define OUTD     1024
#define NEXP     8

// Scratch (allocation-free rule: __device__ globals)
__device__ __half g_x_h[T_TOKENS * DIM];          // 16 MB
__device__ __half g_w_h[NEXP * OUTD * DIM];       // 16 MB
__device__ int    g_cnt[NEXP];
__device__ int    g_tok[NEXP * T_TOKENS];
__device__ float  g_wt [NEXP * T_TOKENS];

// ---------------------------------------------------------------------------
// Kernel 1: zero d_out + counters, convert W -> fp16 scratch.
// 524288 threads: each converts 2x(8 floats) of W and zeroes 4 float4 of out.
// ---------------------------------------------------------------------------
__global__ void __launch_bounds__(256) prep_kernel(const float4* __restrict__ W,
                                                   float4* __restrict__ out4) {
    if (blockIdx.x == 0 && threadIdx.x < NEXP) g_cnt[threadIdx.x] = 0;
    const int gid = blockIdx.x * blockDim.x + threadIdx.x;
    const int stride = gridDim.x * blockDim.x;          // 524288

    uint4* wh = reinterpret_cast<uint4*>(g_w_h);
    // W: 8M floats = 1M groups of 8; 2 groups per thread, batched loads.
    float4 v[4];
#pragma unroll
    for (int i = 0; i < 2; i++) {
        int j = gid + i * stride;
        v[2 * i]     = W[2 * j];
        v[2 * i + 1] = W[2 * j + 1];
    }
#pragma unroll
    for (int i = 0; i < 2; i++) {
        int j = gid + i * stride;
        __half2 h0 = __float22half2_rn(make_float2(v[2*i].x,   v[2*i].y));
        __half2 h1 = __float22half2_rn(make_float2(v[2*i].z,   v[2*i].w));
        __half2 h2 = __float22half2_rn(make_float2(v[2*i+1].x, v[2*i+1].y));
        __half2 h3 = __float22half2_rn(make_float2(v[2*i+1].z, v[2*i+1].w));
        uint4 p;
        p.x = *(uint32_t*)&h0; p.y = *(uint32_t*)&h1;
        p.z = *(uint32_t*)&h2; p.w = *(uint32_t*)&h3;
        wh[j] = p;
    }
    // out: 8M floats = 2M float4; 4 per thread.
    float4 z = make_float4(0.f, 0.f, 0.f, 0.f);
#pragma unroll
    for (int i = 0; i < 4; i++) out4[gid + i * stride] = z;
}

// ---------------------------------------------------------------------------
// Kernel 2: gating (exact fp32), top-2 routing, and x -> fp16 scratch.
// 1 warp per token, 8 tokens per 256-thread CTA, Wg staged in SMEM.
// ---------------------------------------------------------------------------
__global__ void __launch_bounds__(256) gating_kernel(const float* __restrict__ x,
                                                     const float* __restrict__ wg,
                                                     const float* __restrict__ bg) {
    __shared__ float4 s_wg[NEXP * DIM / 4];  // 32 KB
    const int tid = threadIdx.x;
    const float4* wg4 = (const float4*)wg;
    for (int i = tid; i < NEXP * DIM / 4; i += 256) s_wg[i] = wg4[i];
    __syncthreads();

    const int lid = tid & 31;
    const int t = blockIdx.x * 8 + (tid >> 5);
    const float4* xr = (const float4*)(x + (size_t)t * DIM);
    uint2* xo = (uint2*)(g_x_h + (size_t)t * DIM);

    float acc[NEXP];
#pragma unroll
    for (int e = 0; e < NEXP; e++) acc[e] = 0.f;

#pragma unroll
    for (int j = 0; j < 8; j++) {
        int c = lid + j * 32;
        float4 v = xr[c];
        __half2 h0 = __float22half2_rn(make_float2(v.x, v.y));
        __half2 h1 = __float22half2_rn(make_float2(v.z, v.w));
        uint2 p; p.x = *(uint32_t*)&h0; p.y = *(uint32_t*)&h1;
        xo[c] = p;
#pragma unroll
        for (int e = 0; e < NEXP; e++) {
            float4 w = s_wg[e * 256 + c];
            acc[e] += v.x * w.x + v.y * w.y + v.z * w.z + v.w * w.w;
        }
    }
#pragma unroll
    for (int e = 0; e < NEXP; e++) {
#pragma unroll
        for (int o = 16; o > 0; o >>= 1)
            acc[e] += __shfl_xor_sync(0xFFFFFFFFu, acc[e], o);
    }

    if (lid == 0) {
        float l[NEXP];
#pragma unroll
        for (int e = 0; e < NEXP; e++) l[e] = acc[e] + bg[e];  // TEMP = 1
        int i0 = 0;
#pragma unroll
        for (int e = 1; e < NEXP; e++) if (l[e] > l[i0]) i0 = e;
        int i1 = -1;
#pragma unroll
        for (int e = 0; e < NEXP; e++) {
            if (e == i0) continue;
            if (i1 < 0 || l[e] > l[i1]) i1 = e;
        }
        float mx = l[0];
#pragma unroll
        for (int e = 1; e < NEXP; e++) mx = fmaxf(mx, l[e]);
        float s = 0.f;
#pragma unroll
        for (int e = 0; e < NEXP; e++) s += expf(l[e] - mx);
        float inv = 1.f / s;
        float w0 = expf(l[i0] - mx) * inv;
        float w1 = expf(l[i1] - mx) * inv;
        int p0 = atomicAdd(&g_cnt[i0], 1);
        g_tok[i0 * T_TOKENS + p0] = t; g_wt[i0 * T_TOKENS + p0] = w0;
        int p1 = atomicAdd(&g_cnt[i1], 1);
        g_tok[i1 * T_TOKENS + p1] = t; g_wt[i1 * T_TOKENS + p1] = w1;
    }
}

// ---------------------------------------------------------------------------
// sm_100-portable helpers
// ---------------------------------------------------------------------------
__device__ __forceinline__ uint32_t smem_u32(const void* p) {
    uint32_t a;
    asm("{ .reg .u64 t; cvta.to.shared.u64 t, %1; cvt.u32.u64 %0, t; }"
        : "=r"(a) : "l"(p));
    return a;
}
__device__ __forceinline__ void cp16(uint32_t dst, const void* src, uint32_t sz) {
    asm volatile("cp.async.cg.shared.global [%0], [%1], 16, %2;"
                 :: "r"(dst), "l"(src), "r"(sz) : "memory");
}
__device__ __forceinline__ void ldm_x4(uint32_t* r, uint32_t addr) {
    asm volatile("ldmatrix.sync.aligned.m8n8.x4.shared.b16 {%0,%1,%2,%3}, [%4];"
                 : "=r"(r[0]), "=r"(r[1]), "=r"(r[2]), "=r"(r[3]) : "r"(addr));
}
__device__ __forceinline__ void mma_f16(float* c, const uint32_t* a,
                                        uint32_t b0, uint32_t b1) {
    asm volatile(
        "mma.sync.aligned.m16n8k16.row.col.f32.f16.f16.f32 "
        "{%0,%1,%2,%3}, {%4,%5,%6,%7}, {%8,%9}, {%0,%1,%2,%3};"
        : "+f"(c[0]), "+f"(c[1]), "+f"(c[2]), "+f"(c[3])
        : "r"(a[0]), "r"(a[1]), "r"(a[2]), "r"(a[3]), "r"(b0), "r"(b1));
}
__device__ __forceinline__ void red2(float* p, float a, float b) {
    asm volatile("red.relaxed.gpu.global.add.v2.f32 [%0], {%1, %2};"
                 :: "l"(p), "f"(a), "f"(b) : "memory");
}

// ---------------------------------------------------------------------------
// Kernel 3: routed GEMM. grid = (8 N-tiles, 64 M-tiles, 8 experts).
// 128x128x1024 per CTA; BK=32 (fp16); 8 warps in 2x4 -> warp tile 64x32.
// SMEM rows k-contiguous, pitch 40 halves (80 B) -> ldmatrix row addresses
// cycle all 8 16B-quadrants (conflict-free). 3-stage cp.async pipeline.
// mma.m16n8k16 fp16, fp32 accumulators (64/thread).
// SMEM: sA 3*10240 + sB 3*10240 + tok 512 + wt 512 = 62464 B.
// ---------------------------------------------------------------------------
#define PITCH_H 40        // halves per smem row (80 B)
#define STAGE_B 10240     // bytes per operand stage (128 rows * 80 B)

__global__ void __launch_bounds__(256, 2)
moe_gemm_kernel(const float* __restrict__ bias, float* __restrict__ out) {
    extern __shared__ char smem[];
    const int e  = blockIdx.z;
    const int mt = blockIdx.y;
    const int nt = blockIdx.x;
    const int cnt = g_cnt[e];
    if (mt * 128 >= cnt) return;

    const int tid  = threadIdx.x;
    const int wid  = tid >> 5;
    const int lane = tid & 31;
    const int wm   = wid & 1;   // 2 m-blocks of 64
    const int wn   = wid >> 1;  // 4 n-blocks of 32

    char* sA = smem;
    char* sB = smem + 3 * STAGE_B;
    int*   sTok = (int*)(smem + 6 * STAGE_B);
    float* sWt  = (float*)(smem + 6 * STAGE_B + 512);

    if (tid < 128) {
        int idx = mt * 128 + tid;
        int tok = -1; float w = 0.f;
        if (idx < cnt) { tok = g_tok[e * T_TOKENS + idx]; w = g_wt[e * T_TOKENS + idx]; }
        sTok[tid] = tok; sWt[tid] = w;
    }
    __syncthreads();

    // --- per-thread load slots: f = tid + i*256, i<2 -> A, i>=2 -> B ---
    // Each stage row = 32 halves = 64 B = 4 x 16B chunks. 512 slots/operand.
    const __half* aSrc[2];
    uint32_t      aSz[2];
    const __half* bSrc[2];
    uint32_t      dstOff[2];
    const __half* wrow = g_w_h + ((size_t)(e * OUTD + nt * 128)) * DIM;
#pragma unroll
    for (int i = 0; i < 2; i++) {
        int f = tid + i * 256;
        int r = f >> 2, q = f & 3;   // r = tile row, q = 16B chunk (8 halves)
        int tok = sTok[r];
        aSrc[i] = (tok >= 0 ? g_x_h + (size_t)tok * DIM : g_x_h) + q * 8;
        aSz[i]  = (tok >= 0) ? 16u : 0u;   // zfill padding rows
        bSrc[i] = wrow + (size_t)r * DIM + q * 8;
        dstOff[i] = (uint32_t)(r * 80 + q * 16);
    }

    const uint32_t aBase = smem_u32(sA);
    const uint32_t bBase = smem_u32(sB);

    auto prefetch = [&](int s, int buf) {
        uint32_t st = (uint32_t)buf * STAGE_B;
        int ko = s * 32;  // half offset along K
#pragma unroll
        for (int i = 0; i < 2; i++) cp16(aBase + st + dstOff[i], aSrc[i] + ko, aSz[i]);
#pragma unroll
        for (int i = 0; i < 2; i++) cp16(bBase + st + dstOff[i], bSrc[i] + ko, 16u);
    };

    prefetch(0, 0);
    asm volatile("cp.async.commit_group;" ::: "memory");
    prefetch(1, 1);
    asm volatile("cp.async.commit_group;" ::: "memory");
    prefetch(2, 2);
    asm volatile("cp.async.commit_group;" ::: "memory");

    // ldmatrix fragment addresses (bytes)
    // A (m16k16, x4): row = wm*64 + mf*16 + (lane&15); kbyte = (lane>>4)*16 + kk*32
    // B (n16k16, x4): row = wn*32 + pr*16 + ((lane>>4)&1)*8 + (lane&7);
    //                 kbyte = ((lane>>3)&1)*16 + kk*32
    const uint32_t aAddr0 = aBase + (uint32_t)((wm * 64 + (lane & 15)) * 80)
                                  + (uint32_t)((lane >> 4) * 16);
    const uint32_t bAddr0 = bBase + (uint32_t)((wn * 32 + ((lane >> 4) << 3) + (lane & 7)) * 80)
                                  + (uint32_t)(((lane >> 3) & 1) * 16);

    float c[4][4][4];
#pragma unroll
    for (int mf = 0; mf < 4; mf++)
#pragma unroll
        for (int nf = 0; nf < 4; nf++)
#pragma unroll
            for (int j = 0; j < 4; j++) c[mf][nf][j] = 0.f;

    int buf = 0;
    for (int s = 0; s < 32; s++) {
        asm volatile("cp.async.wait_group 2;" ::: "memory");
        __syncthreads();
        const uint32_t sa = aAddr0 + (uint32_t)buf * STAGE_B;
        const uint32_t sb = bAddr0 + (uint32_t)buf * STAGE_B;
#pragma unroll
        for (int kk = 0; kk < 2; kk++) {
            uint32_t a[4][4];
#pragma unroll
            for (int mf = 0; mf < 4; mf++)
                ldm_x4(a[mf], sa + (uint32_t)(mf * 16 * 80) + (uint32_t)(kk * 32));
            uint32_t b[2][4];
#pragma unroll
            for (int pr = 0; pr < 2; pr++)
                ldm_x4(b[pr], sb + (uint32_t)(pr * 16 * 80) + (uint32_t)(kk * 32));
#pragma unroll
            for (int mf = 0; mf < 4; mf++)
#pragma unroll
                for (int nf = 0; nf < 4; nf++)
                    mma_f16(c[mf][nf], a[mf],
                            b[nf >> 1][(nf & 1) * 2], b[nf >> 1][(nf & 1) * 2 + 1]);
        }
        __syncthreads();
        if (s + 3 < 32) prefetch(s + 3, buf);
        asm volatile("cp.async.commit_group;" ::: "memory");
        buf = (buf == 2) ? 0 : buf + 1;
    }

    // --- epilogue: bias + gate-weight scale + vectorized global reduction ---
    const int nbase = nt * 128;
    const float* bptr = bias + e * OUTD + nbase;
#pragma unroll
    for (int mf = 0; mf < 4; mf++) {
        int m0 = wm * 64 + mf * 16 + (lane >> 2);
        int m1 = m0 + 8;
        int t0 = sTok[m0], t1 = sTok[m1];
        float w0 = sWt[m0], w1 = sWt[m1];
#pragma unroll
        for (int nf = 0; nf < 4; nf++) {
            int col = wn * 32 + nf * 8 + 2 * (lane & 3);
            float2 bb = *(const float2*)(bptr + col);
            if (t0 >= 0) {
                red2(out + (size_t)t0 * OUTD + nbase + col,
                     w0 * (c[mf][nf][0] + bb.x), w0 * (c[mf][nf][1] + bb.y));
            }
            if (t1 >= 0) {
                red2(out + (size_t)t1 * OUTD + nbase + col,
                     w1 * (c[mf][nf][2] + bb.x), w1 * (c[mf][nf][3] + bb.y));
            }
        }
    }
}

// ---------------------------------------------------------------------------
extern "C" void kernel_launch(void* const* d_in, const int* in_sizes, int n_in,
                              void* d_out, int out_size) {
    const float* x  = (const float*)d_in[0];   // [4,2048,1024]
    const float* W  = (const float*)d_in[1];   // [8,1024,1024]
    const float* b  = (const float*)d_in[2];   // [8,1024]
    const float* Wg = (const float*)d_in[3];   // [8,1024]
    const float* bg = (const float*)d_in[4];   // [8]
    float* out = (float*)d_out;                // [4,2048,1024] f32

    static bool attr_set = false;
    if (!attr_set) {
        cudaFuncSetAttribute(moe_gemm_kernel,
                             cudaFuncAttributeMaxDynamicSharedMemorySize, 62464);
        attr_set = true;
    }

    prep_kernel<<<2048, 256>>>((const float4*)W, (float4*)out);
    gating_kernel<<<1024, 256>>>(x, Wg, bg);
    dim3 grid(8, 64, 8);
    moe_gemm_kernel<<<grid, 256, 62464>>>(b, out);
}

// round 8
// speedup vs baseline: 1.5804x; 1.0333x over previous
#include <cuda_runtime.h>
#include <cuda_fp16.h>
#include <cstdint>

// ---------------------------------------------------------------------------
// MoE top-2 projection: out[t] = sum_k w_k * (x[t] @ W[e_k]^T + b[e_k])
// x:[8192,1024] f32, W:[8,1024,1024], b:[8,1024], Wg:[8,1024], bg:[8]
// Route -> per-expert gathered GEMM with mma.sync fp16 (f32 accumulate).
// Launch pattern per call: [memset g_cnt, fused prep+gating, routed GEMM].
// ---------------------------------------------------------------------------

#define T_TOKENS 8192
#define DIM      1024
#define OUTD     1024
#define NEXP     8

// Scratch (allocation-free rule: __device__ globals)
__device__ __half g_x_h[T_TOKENS * DIM];          // 16 MB
__device__ __half g_w_h[NEXP * OUTD * DIM];       // 16 MB
__device__ int    g_cnt[NEXP];                    // zeroed via cudaMemsetAsync
__device__ int    g_tok[NEXP * T_TOKENS];
__device__ float  g_wt [NEXP * T_TOKENS];

// ---------------------------------------------------------------------------
// Kernel 1 (fused): blocks [0,1024) = gating + x->fp16; blocks [1024,3072) =
// W->fp16 conversion + zero-init of d_out. Independent work, one launch.
// ---------------------------------------------------------------------------
__global__ void __launch_bounds__(256)
fused_prep_gating(const float* __restrict__ x,
                  const float4* __restrict__ W,
                  const float* __restrict__ wg,
                  const float* __restrict__ bg,
                  float4* __restrict__ out4) {
    __shared__ float4 s_wg[NEXP * DIM / 4];  // 32 KB (gating blocks only)
    const int tid = threadIdx.x;

    if (blockIdx.x >= 1024) {
        // ---- prep part: W fp16 convert + out zero ----
        const int gid = (blockIdx.x - 1024) * 256 + tid;
        const int stride = 2048 * 256;        // 524288
        uint4* wh = reinterpret_cast<uint4*>(g_w_h);
        float4 v[4];
#pragma unroll
        for (int i = 0; i < 2; i++) {
            int j = gid + i * stride;
            v[2 * i]     = W[2 * j];
            v[2 * i + 1] = W[2 * j + 1];
        }
#pragma unroll
        for (int i = 0; i < 2; i++) {
            int j = gid + i * stride;
            __half2 h0 = __float22half2_rn(make_float2(v[2*i].x,   v[2*i].y));
            __half2 h1 = __float22half2_rn(make_float2(v[2*i].z,   v[2*i].w));
            __half2 h2 = __float22half2_rn(make_float2(v[2*i+1].x, v[2*i+1].y));
            __half2 h3 = __float22half2_rn(make_float2(v[2*i+1].z, v[2*i+1].w));
            uint4 p;
            p.x = *(uint32_t*)&h0; p.y = *(uint32_t*)&h1;
            p.z = *(uint32_t*)&h2; p.w = *(uint32_t*)&h3;
            wh[j] = p;
        }
        float4 z = make_float4(0.f, 0.f, 0.f, 0.f);
#pragma unroll
        for (int i = 0; i < 4; i++) out4[gid + i * stride] = z;
        return;
    }

    // ---- gating part: exact fp32 gate, top-2 route, x -> fp16 ----
    const float4* wg4 = (const float4*)wg;
    for (int i = tid; i < NEXP * DIM / 4; i += 256) s_wg[i] = wg4[i];
    __syncthreads();

    const int lid = tid & 31;
    const int t = blockIdx.x * 8 + (tid >> 5);
    const float4* xr = (const float4*)(x + (size_t)t * DIM);
    uint2* xo = (uint2*)(g_x_h + (size_t)t * DIM);

    float acc[NEXP];
#pragma unroll
    for (int e = 0; e < NEXP; e++) acc[e] = 0.f;

#pragma unroll
    for (int j = 0; j < 8; j++) {
        int c = lid + j * 32;
        float4 v = xr[c];
        __half2 h0 = __float22half2_rn(make_float2(v.x, v.y));
        __half2 h1 = __float22half2_rn(make_float2(v.z, v.w));
        uint2 p; p.x = *(uint32_t*)&h0; p.y = *(uint32_t*)&h1;
        xo[c] = p;
#pragma unroll
        for (int e = 0; e < NEXP; e++) {
            float4 w = s_wg[e * 256 + c];
            acc[e] += v.x * w.x + v.y * w.y + v.z * w.z + v.w * w.w;
        }
    }
#pragma unroll
    for (int e = 0; e < NEXP; e++) {
#pragma unroll
        for (int o = 16; o > 0; o >>= 1)
            acc[e] += __shfl_xor_sync(0xFFFFFFFFu, acc[e], o);
    }

    if (lid == 0) {
        float l[NEXP];
#pragma unroll
        for (int e = 0; e < NEXP; e++) l[e] = acc[e] + bg[e];  // TEMP = 1
        int i0 = 0;
#pragma unroll
        for (int e = 1; e < NEXP; e++) if (l[e] > l[i0]) i0 = e;
        int i1 = -1;
#pragma unroll
        for (int e = 0; e < NEXP; e++) {
            if (e == i0) continue;
            if (i1 < 0 || l[e] > l[i1]) i1 = e;
        }
        float mx = l[0];
#pragma unroll
        for (int e = 1; e < NEXP; e++) mx = fmaxf(mx, l[e]);
        float s = 0.f;
#pragma unroll
        for (int e = 0; e < NEXP; e++) s += expf(l[e] - mx);
        float inv = 1.f / s;
        float w0 = expf(l[i0] - mx) * inv;
        float w1 = expf(l[i1] - mx) * inv;
        int p0 = atomicAdd(&g_cnt[i0], 1);
        g_tok[i0 * T_TOKENS + p0] = t; g_wt[i0 * T_TOKENS + p0] = w0;
        int p1 = atomicAdd(&g_cnt[i1], 1);
        g_tok[i1 * T_TOKENS + p1] = t; g_wt[i1 * T_TOKENS + p1] = w1;
    }
}

// ---------------------------------------------------------------------------
// sm_100-portable helpers
// ---------------------------------------------------------------------------
__device__ __forceinline__ uint32_t smem_u32(const void* p) {
    uint32_t a;
    asm("{ .reg .u64 t; cvta.to.shared.u64 t, %1; cvt.u32.u64 %0, t; }"
        : "=r"(a) : "l"(p));
    return a;
}
__device__ __forceinline__ void cp16(uint32_t dst, const void* src, uint32_t sz) {
    asm volatile("cp.async.cg.shared.global [%0], [%1], 16, %2;"
                 :: "r"(dst), "l"(src), "r"(sz) : "memory");
}
__device__ __forceinline__ void ldm_x4(uint32_t* r, uint32_t addr) {
    asm volatile("ldmatrix.sync.aligned.m8n8.x4.shared.b16 {%0,%1,%2,%3}, [%4];"
                 : "=r"(r[0]), "=r"(r[1]), "=r"(r[2]), "=r"(r[3]) : "r"(addr));
}
__device__ __forceinline__ void mma_f16(float* c, const uint32_t* a,
                                        uint32_t b0, uint32_t b1) {
    asm volatile(
        "mma.sync.aligned.m16n8k16.row.col.f32.f16.f16.f32 "
        "{%0,%1,%2,%3}, {%4,%5,%6,%7}, {%8,%9}, {%0,%1,%2,%3};"
        : "+f"(c[0]), "+f"(c[1]), "+f"(c[2]), "+f"(c[3])
        : "r"(a[0]), "r"(a[1]), "r"(a[2]), "r"(a[3]), "r"(b0), "r"(b1));
}
__device__ __forceinline__ void red2(float* p, float a, float b) {
    asm volatile("red.relaxed.gpu.global.add.v2.f32 [%0], {%1, %2};"
                 :: "l"(p), "f"(a), "f"(b) : "memory");
}

// ---------------------------------------------------------------------------
// Kernel 2: routed GEMM. grid = (8 N-tiles, 64 M-tiles, 8 experts).
// 128x128x1024 per CTA; BK=32 (fp16); 8 warps in 2x4 -> warp tile 64x32.
// SMEM rows k-contiguous, pitch 40 halves (80 B) -> ldmatrix row addresses
// cycle all 8 16B-quadrants (conflict-free).
// Single-barrier 3-buffer pipeline: wait_group(1) -> bar -> prefetch(s+2 into
// the buffer freed by stage s-1) -> commit -> compute(s). One bar both
// publishes stage s and protects the freed buffer.
// SMEM: sA 3*10240 + sB 3*10240 + tok 512 + wt 512 = 62464 B.
// ---------------------------------------------------------------------------
#define PITCH_H 40        // halves per smem row (80 B)
#define STAGE_B 10240     // bytes per operand stage (128 rows * 80 B)

__global__ void __launch_bounds__(256, 2)
moe_gemm_kernel(const float* __restrict__ bias, float* __restrict__ out) {
    extern __shared__ char smem[];
    const int e  = blockIdx.z;
    const int mt = blockIdx.y;
    const int nt = blockIdx.x;
    const int cnt = g_cnt[e];
    if (mt * 128 >= cnt) return;

    const int tid  = threadIdx.x;
    const int wid  = tid >> 5;
    const int lane = tid & 31;
    const int wm   = wid & 1;   // 2 m-blocks of 64
    const int wn   = wid >> 1;  // 4 n-blocks of 32

    char* sA = smem;
    char* sB = smem + 3 * STAGE_B;
    int*   sTok = (int*)(smem + 6 * STAGE_B);
    float* sWt  = (float*)(smem + 6 * STAGE_B + 512);

    if (tid < 128) {
        int idx = mt * 128 + tid;
        int tok = -1; float w = 0.f;
        if (idx < cnt) { tok = g_tok[e * T_TOKENS + idx]; w = g_wt[e * T_TOKENS + idx]; }
        sTok[tid] = tok; sWt[tid] = w;
    }
    __syncthreads();

    // --- per-thread load slots: 512 16B-chunks per operand, 2 per thread ---
    const __half* aSrc[2];
    uint32_t      aSz[2];
    const __half* bSrc[2];
    uint32_t      dstOff[2];
    const __half* wrow = g_w_h + ((size_t)(e * OUTD + nt * 128)) * DIM;
#pragma unroll
    for (int i = 0; i < 2; i++) {
        int f = tid + i * 256;
        int r = f >> 2, q = f & 3;   // r = tile row, q = 16B chunk (8 halves)
        int tok = sTok[r];
        aSrc[i] = (tok >= 0 ? g_x_h + (size_t)tok * DIM : g_x_h) + q * 8;
        aSz[i]  = (tok >= 0) ? 16u : 0u;   // zfill padding rows
        bSrc[i] = wrow + (size_t)r * DIM + q * 8;
        dstOff[i] = (uint32_t)(r * 80 + q * 16);
    }

    const uint32_t aBase = smem_u32(sA);
    const uint32_t bBase = smem_u32(sB);

    auto prefetch = [&](int s, int buf) {
        uint32_t st = (uint32_t)buf * STAGE_B;
        int ko = s * 32;  // half offset along K
#pragma unroll
        for (int i = 0; i < 2; i++) cp16(aBase + st + dstOff[i], aSrc[i] + ko, aSz[i]);
#pragma unroll
        for (int i = 0; i < 2; i++) cp16(bBase + st + dstOff[i], bSrc[i] + ko, 16u);
    };

    prefetch(0, 0);
    asm volatile("cp.async.commit_group;" ::: "memory");
    prefetch(1, 1);
    asm volatile("cp.async.commit_group;" ::: "memory");

    // ldmatrix fragment addresses (bytes)
    const uint32_t aAddr0 = aBase + (uint32_t)((wm * 64 + (lane & 15)) * 80)
                                  + (uint32_t)((lane >> 4) * 16);
    const uint32_t bAddr0 = bBase + (uint32_t)((wn * 32 + ((lane >> 4) << 3) + (lane & 7)) * 80)
                                  + (uint32_t)(((lane >> 3) & 1) * 16);

    float c[4][4][4];
#pragma unroll
    for (int mf = 0; mf < 4; mf++)
#pragma unroll
        for (int nf = 0; nf < 4; nf++)
#pragma unroll
            for (int j = 0; j < 4; j++) c[mf][nf][j] = 0.f;

    int buf = 0;
    for (int s = 0; s < 32; s++) {
        asm volatile("cp.async.wait_group 1;" ::: "memory");
        __syncthreads();  // stage s visible to all; buffer (s-1)%3 fully read
        if (s + 2 < 32) {
            int nb = (s + 2) % 3;     // == (s-1)%3, the freed buffer
            prefetch(s + 2, nb);
        }
        asm volatile("cp.async.commit_group;" ::: "memory");

        const uint32_t sa = aAddr0 + (uint32_t)buf * STAGE_B;
        const uint32_t sb = bAddr0 + (uint32_t)buf * STAGE_B;
#pragma unroll
        for (int kk = 0; kk < 2; kk++) {
            uint32_t a[4][4];
#pragma unroll
            for (int mf = 0; mf < 4; mf++)
                ldm_x4(a[mf], sa + (uint32_t)(mf * 16 * 80) + (uint32_t)(kk * 32));
            uint32_t b[2][4];
#pragma unroll
            for (int pr = 0; pr < 2; pr++)
                ldm_x4(b[pr], sb + (uint32_t)(pr * 16 * 80) + (uint32_t)(kk * 32));
#pragma unroll
            for (int mf = 0; mf < 4; mf++)
#pragma unroll
                for (int nf = 0; nf < 4; nf++)
                    mma_f16(c[mf][nf], a[mf],
                            b[nf >> 1][(nf & 1) * 2], b[nf >> 1][(nf & 1) * 2 + 1]);
        }
        buf = (buf == 2) ? 0 : buf + 1;
    }

    // --- epilogue: bias + gate-weight scale + vectorized global reduction ---
    const int nbase = nt * 128;
    const float* bptr = bias + e * OUTD + nbase;
#pragma unroll
    for (int mf = 0; mf < 4; mf++) {
        int m0 = wm * 64 + mf * 16 + (lane >> 2);
        int m1 = m0 + 8;
        int t0 = sTok[m0], t1 = sTok[m1];
        float w0 = sWt[m0], w1 = sWt[m1];
#pragma unroll
        for (int nf = 0; nf < 4; nf++) {
            int col = wn * 32 + nf * 8 + 2 * (lane & 3);
            float2 bb = *(const float2*)(bptr + col);
            if (t0 >= 0) {
                red2(out + (size_t)t0 * OUTD + nbase + col,
                     w0 * (c[mf][nf][0] + bb.x), w0 * (c[mf][nf][1] + bb.y));
            }
            if (t1 >= 0) {
                red2(out + (size_t)t1 * OUTD + nbase + col,
                     w1 * (c[mf][nf][2] + bb.x), w1 * (c[mf][nf][3] + bb.y));
            }
        }
    }
}

// ---------------------------------------------------------------------------
extern "C" void kernel_launch(void* const* d_in, const int* in_sizes, int n_in,
                              void* d_out, int out_size) {
    const float* x  = (const float*)d_in[0];   // [4,2048,1024]
    const float* W  = (const float*)d_in[1];   // [8,1024,1024]
    const float* b  = (const float*)d_in[2];   // [8,1024]
    const float* Wg = (const float*)d_in[3];   // [8,1024]
    const float* bg = (const float*)d_in[4];   // [8]
    float* out = (float*)d_out;                // [4,2048,1024] f32

    static void* cnt_addr = nullptr;
    if (!cnt_addr) {
        cudaGetSymbolAddress(&cnt_addr, g_cnt);
        cudaFuncSetAttribute(moe_gemm_kernel,
                             cudaFuncAttributeMaxDynamicSharedMemorySize, 62464);
    }

    cudaMemsetAsync(cnt_addr, 0, NEXP * sizeof(int));
    fused_prep_gating<<<3072, 256>>>(x, (const float4*)W, Wg, bg, (float4*)out);
    dim3 grid(8, 64, 8);
    moe_gemm_kernel<<<grid, 256, 62464>>>(b, out);
}

// round 9
// speedup vs baseline: 1.6991x; 1.0751x over previous
#include <cuda_runtime.h>
#include <cuda_fp16.h>
#include <cstdint>

// ---------------------------------------------------------------------------
// MoE top-2 projection: out[t] = sum_k w_k * (x[t] @ W[e_k]^T + b[e_k])
// x:[8192,1024] f32, W:[8,1024,1024], b:[8,1024], Wg:[8,1024], bg:[8]
// Route -> per-expert gathered GEMM with mma.sync fp16 (f32 accumulate).
// GEMM shape: CTA 128x256, 8 warps of 64x64, 1 CTA/SM, register fragment
// double-buffering across kk and across stage boundary (CUTLASS sm80 style).
// ---------------------------------------------------------------------------

#define T_TOKENS 8192
#define DIM      1024
#define OUTD     1024
#define NEXP     8

// Scratch (allocation-free rule: __device__ globals)
__device__ __half g_x_h[T_TOKENS * DIM];          // 16 MB
__device__ __half g_w_h[NEXP * OUTD * DIM];       // 16 MB
__device__ int    g_cnt[NEXP];                    // zeroed via cudaMemsetAsync
__device__ int    g_tok[NEXP * T_TOKENS];
__device__ float  g_wt [NEXP * T_TOKENS];

// ---------------------------------------------------------------------------
// Kernel 1 (fused): blocks [0,1024) = gating + x->fp16; blocks [1024,3072) =
// W->fp16 conversion + zero-init of d_out. Independent work, one launch.
// ---------------------------------------------------------------------------
__global__ void __launch_bounds__(256)
fused_prep_gating(const float* __restrict__ x,
                  const float4* __restrict__ W,
                  const float* __restrict__ wg,
                  const float* __restrict__ bg,
                  float4* __restrict__ out4) {
    __shared__ float4 s_wg[NEXP * DIM / 4];  // 32 KB (gating blocks only)
    const int tid = threadIdx.x;

    if (blockIdx.x >= 1024) {
        // ---- prep part: W fp16 convert + out zero ----
        const int gid = (blockIdx.x - 1024) * 256 + tid;
        const int stride = 2048 * 256;        // 524288
        uint4* wh = reinterpret_cast<uint4*>(g_w_h);
        float4 v[4];
#pragma unroll
        for (int i = 0; i < 2; i++) {
            int j = gid + i * stride;
            v[2 * i]     = W[2 * j];
            v[2 * i + 1] = W[2 * j + 1];
        }
#pragma unroll
        for (int i = 0; i < 2; i++) {
            int j = gid + i * stride;
            __half2 h0 = __float22half2_rn(make_float2(v[2*i].x,   v[2*i].y));
            __half2 h1 = __float22half2_rn(make_float2(v[2*i].z,   v[2*i].w));
            __half2 h2 = __float22half2_rn(make_float2(v[2*i+1].x, v[2*i+1].y));
            __half2 h3 = __float22half2_rn(make_float2(v[2*i+1].z, v[2*i+1].w));
            uint4 p;
            p.x = *(uint32_t*)&h0; p.y = *(uint32_t*)&h1;
            p.z = *(uint32_t*)&h2; p.w = *(uint32_t*)&h3;
            wh[j] = p;
        }
        float4 z = make_float4(0.f, 0.f, 0.f, 0.f);
#pragma unroll
        for (int i = 0; i < 4; i++) out4[gid + i * stride] = z;
        return;
    }

    // ---- gating part: exact fp32 gate, top-2 route, x -> fp16 ----
    const float4* wg4 = (const float4*)wg;
    for (int i = tid; i < NEXP * DIM / 4; i += 256) s_wg[i] = wg4[i];
    __syncthreads();

    const int lid = tid & 31;
    const int t = blockIdx.x * 8 + (tid >> 5);
    const float4* xr = (const float4*)(x + (size_t)t * DIM);
    uint2* xo = (uint2*)(g_x_h + (size_t)t * DIM);

    float acc[NEXP];
#pragma unroll
    for (int e = 0; e < NEXP; e++) acc[e] = 0.f;

#pragma unroll
    for (int j = 0; j < 8; j++) {
        int c = lid + j * 32;
        float4 v = xr[c];
        __half2 h0 = __float22half2_rn(make_float2(v.x, v.y));
        __half2 h1 = __float22half2_rn(make_float2(v.z, v.w));
        uint2 p; p.x = *(uint32_t*)&h0; p.y = *(uint32_t*)&h1;
        xo[c] = p;
#pragma unroll
        for (int e = 0; e < NEXP; e++) {
            float4 w = s_wg[e * 256 + c];
            acc[e] += v.x * w.x + v.y * w.y + v.z * w.z + v.w * w.w;
        }
    }
#pragma unroll
    for (int e = 0; e < NEXP; e++) {
#pragma unroll
        for (int o = 16; o > 0; o >>= 1)
            acc[e] += __shfl_xor_sync(0xFFFFFFFFu, acc[e], o);
    }

    if (lid == 0) {
        float l[NEXP];
#pragma unroll
        for (int e = 0; e < NEXP; e++) l[e] = acc[e] + bg[e];  // TEMP = 1
        int i0 = 0;
#pragma unroll
        for (int e = 1; e < NEXP; e++) if (l[e] > l[i0]) i0 = e;
        int i1 = -1;
#pragma unroll
        for (int e = 0; e < NEXP; e++) {
            if (e == i0) continue;
            if (i1 < 0 || l[e] > l[i1]) i1 = e;
        }
        float mx = l[0];
#pragma unroll
        for (int e = 1; e < NEXP; e++) mx = fmaxf(mx, l[e]);
        float s = 0.f;
#pragma unroll
        for (int e = 0; e < NEXP; e++) s += expf(l[e] - mx);
        float inv = 1.f / s;
        float w0 = expf(l[i0] - mx) * inv;
        float w1 = expf(l[i1] - mx) * inv;
        int p0 = atomicAdd(&g_cnt[i0], 1);
        g_tok[i0 * T_TOKENS + p0] = t; g_wt[i0 * T_TOKENS + p0] = w0;
        int p1 = atomicAdd(&g_cnt[i1], 1);
        g_tok[i1 * T_TOKENS + p1] = t; g_wt[i1 * T_TOKENS + p1] = w1;
    }
}

// ---------------------------------------------------------------------------
// sm_100-portable helpers
// ---------------------------------------------------------------------------
__device__ __forceinline__ uint32_t smem_u32(const void* p) {
    uint32_t a;
    asm("{ .reg .u64 t; cvta.to.shared.u64 t, %1; cvt.u32.u64 %0, t; }"
        : "=r"(a) : "l"(p));
    return a;
}
__device__ __forceinline__ void cp16(uint32_t dst, const void* src, uint32_t sz) {
    asm volatile("cp.async.cg.shared.global [%0], [%1], 16, %2;"
                 :: "r"(dst), "l"(src), "r"(sz) : "memory");
}
__device__ __forceinline__ void ldm_x4(uint32_t* r, uint32_t addr) {
    asm volatile("ldmatrix.sync.aligned.m8n8.x4.shared.b16 {%0,%1,%2,%3}, [%4];"
                 : "=r"(r[0]), "=r"(r[1]), "=r"(r[2]), "=r"(r[3]) : "r"(addr));
}
__device__ __forceinline__ void mma_f16(float* c, const uint32_t* a,
                                        uint32_t b0, uint32_t b1) {
    asm volatile(
        "mma.sync.aligned.m16n8k16.row.col.f32.f16.f16.f32 "
        "{%0,%1,%2,%3}, {%4,%5,%6,%7}, {%8,%9}, {%0,%1,%2,%3};"
        : "+f"(c[0]), "+f"(c[1]), "+f"(c[2]), "+f"(c[3])
        : "r"(a[0]), "r"(a[1]), "r"(a[2]), "r"(a[3]), "r"(b0), "r"(b1));
}
__device__ __forceinline__ void red2(float* p, float a, float b) {
    asm volatile("red.relaxed.gpu.global.add.v2.f32 [%0], {%1, %2};"
                 :: "l"(p), "f"(a), "f"(b) : "memory");
}

// ---------------------------------------------------------------------------
// Kernel 2: routed GEMM. grid = (4 N-tiles, 64 M-tiles, 8 experts).
// 128x256x1024 per CTA; BK=32 (fp16); 8 warps in 2x4 -> warp tile 64x64.
// 1 CTA/SM (~220 regs): register fragment double-buffering across kk and
// across the stage boundary — per stage:
//   bar; prefetch(s+2); ldsm kk0(s); mma kk1(s-1); ldsm kk1(s); mma kk0(s)
// so every mma block is preceded by an independent ldsm block.
// SMEM pitch 40 halves (80 B), 3 stages: A 3*10240 + B 3*20480 + 1K = 93184 B.
// ---------------------------------------------------------------------------
#define PITCH_B  80       // bytes per smem row
#define STG_A    10240    // 128 rows * 80 B
#define STG_B    20480    // 256 rows * 80 B

__global__ void __launch_bounds__(256, 1)
moe_gemm_kernel(const float* __restrict__ bias, float* __restrict__ out) {
    extern __shared__ char smem[];
    const int e  = blockIdx.z;
    const int mt = blockIdx.y;
    const int nt = blockIdx.x;
    const int cnt = g_cnt[e];
    if (mt * 128 >= cnt) return;

    const int tid  = threadIdx.x;
    const int wid  = tid >> 5;
    const int lane = tid & 31;
    const int wm   = wid & 1;   // 2 m-blocks of 64
    const int wn   = wid >> 1;  // 4 n-blocks of 64

    char* sA = smem;
    char* sB = smem + 3 * STG_A;
    int*   sTok = (int*)(smem + 3 * STG_A + 3 * STG_B);
    float* sWt  = (float*)(smem + 3 * STG_A + 3 * STG_B + 512);

    if (tid < 128) {
        int idx = mt * 128 + tid;
        int tok = -1; float w = 0.f;
        if (idx < cnt) { tok = g_tok[e * T_TOKENS + idx]; w = g_wt[e * T_TOKENS + idx]; }
        sTok[tid] = tok; sWt[tid] = w;
    }
    __syncthreads();

    // --- cp.async slots. A: 512 chunks (2/thread); B: 1024 chunks (4/thread)
    const __half* aSrc[2];
    uint32_t      aSz[2];
    uint32_t      aOff[2];
    const __half* bSrc[4];
    uint32_t      bOff[4];
    const __half* wrow = g_w_h + ((size_t)(e * OUTD + nt * 256)) * DIM;
#pragma unroll
    for (int i = 0; i < 2; i++) {
        int f = tid + i * 256;
        int r = f >> 2, q = f & 3;   // A row, 16B chunk
        int tok = sTok[r];
        aSrc[i] = (tok >= 0 ? g_x_h + (size_t)tok * DIM : g_x_h) + q * 8;
        aSz[i]  = (tok >= 0) ? 16u : 0u;   // zfill padding rows
        aOff[i] = (uint32_t)(r * PITCH_B + q * 16);
    }
#pragma unroll
    for (int i = 0; i < 4; i++) {
        int f = tid + i * 256;
        int r = f >> 2, q = f & 3;   // B row (0..255), 16B chunk
        bSrc[i] = wrow + (size_t)r * DIM + q * 8;
        bOff[i] = (uint32_t)(r * PITCH_B + q * 16);
    }

    const uint32_t aBase = smem_u32(sA);
    const uint32_t bBase = smem_u32(sB);

    auto prefetch = [&](int s, int buf) {
        uint32_t sta = (uint32_t)buf * STG_A;
        uint32_t stb = (uint32_t)buf * STG_B;
        int ko = s * 32;  // half offset along K
#pragma unroll
        for (int i = 0; i < 2; i++) cp16(aBase + sta + aOff[i], aSrc[i] + ko, aSz[i]);
#pragma unroll
        for (int i = 0; i < 4; i++) cp16(bBase + stb + bOff[i], bSrc[i] + ko, 16u);
    };

    prefetch(0, 0);
    asm volatile("cp.async.commit_group;" ::: "memory");
    prefetch(1, 1);
    asm volatile("cp.async.commit_group;" ::: "memory");

    // ldmatrix fragment base addresses (per-buffer offsets added in loop)
    const uint32_t aA0 = aBase + (uint32_t)((wm * 64 + (lane & 15)) * PITCH_B)
                               + (uint32_t)((lane >> 4) * 16);
    const uint32_t bA0 = bBase + (uint32_t)((wn * 64 + ((lane >> 4) << 3) + (lane & 7)) * PITCH_B)
                               + (uint32_t)(((lane >> 3) & 1) * 16);

    float c[4][8][4];
#pragma unroll
    for (int mf = 0; mf < 4; mf++)
#pragma unroll
        for (int nf = 0; nf < 8; nf++)
#pragma unroll
            for (int j = 0; j < 4; j++) c[mf][nf][j] = 0.f;

    uint32_t af[2][4][4];   // [kk-slot][mf][reg]
    uint32_t bf[2][4][4];   // [kk-slot][pr][reg]

    auto ldsFrag = [&](int slot, uint32_t sa, uint32_t sb, int kk) {
#pragma unroll
        for (int mf = 0; mf < 4; mf++)
            ldm_x4(af[slot][mf], sa + (uint32_t)(mf * 16 * PITCH_B) + (uint32_t)(kk * 32));
#pragma unroll
        for (int pr = 0; pr < 4; pr++)
            ldm_x4(bf[slot][pr], sb + (uint32_t)(pr * 16 * PITCH_B) + (uint32_t)(kk * 32));
    };
    auto mmaBlk = [&](int slot) {
#pragma unroll
        for (int mf = 0; mf < 4; mf++)
#pragma unroll
            for (int nf = 0; nf < 8; nf++)
                mma_f16(c[mf][nf], af[slot][mf],
                        bf[slot][nf >> 1][(nf & 1) * 2], bf[slot][nf >> 1][(nf & 1) * 2 + 1]);
    };

    // ---- peeled stage 0 ----
    asm volatile("cp.async.wait_group 1;" ::: "memory");
    __syncthreads();
    prefetch(2, 2);
    asm volatile("cp.async.commit_group;" ::: "memory");
    ldsFrag(0, aA0, bA0, 0);
    ldsFrag(1, aA0, bA0, 1);
    mmaBlk(0);

    for (int s = 1; s < 32; s++) {
        asm volatile("cp.async.wait_group 1;" ::: "memory");
        __syncthreads();  // stage s smem ready; buffer (s-1)%3 fully read
        if (s + 2 < 32) prefetch(s + 2, (s + 2) % 3);
        asm volatile("cp.async.commit_group;" ::: "memory");

        const uint32_t off = (uint32_t)(s % 3);
        const uint32_t sa = aA0 + off * STG_A;
        const uint32_t sb = bA0 + off * STG_B;
        ldsFrag(0, sa, sb, 0);   // stage s, kk0
        mmaBlk(1);               // stage s-1, kk1 (regs only)
        ldsFrag(1, sa, sb, 1);   // stage s, kk1
        mmaBlk(0);               // stage s, kk0
    }
    mmaBlk(1);  // final stage kk1

    // --- epilogue: bias + gate-weight scale + vectorized global reduction ---
    const int nbase = nt * 256;
    const float* bptr = bias + e * OUTD + nbase;
#pragma unroll
    for (int mf = 0; mf < 4; mf++) {
        int m0 = wm * 64 + mf * 16 + (lane >> 2);
        int m1 = m0 + 8;
        int t0 = sTok[m0], t1 = sTok[m1];
        float w0 = sWt[m0], w1 = sWt[m1];
#pragma unroll
        for (int nf = 0; nf < 8; nf++) {
            int col = wn * 64 + nf * 8 + 2 * (lane & 3);
            float2 bb = *(const float2*)(bptr + col);
            if (t0 >= 0) {
                red2(out + (size_t)t0 * OUTD + nbase + col,
                     w0 * (c[mf][nf][0] + bb.x), w0 * (c[mf][nf][1] + bb.y));
            }
            if (t1 >= 0) {
                red2(out + (size_t)t1 * OUTD + nbase + col,
                     w1 * (c[mf][nf][2] + bb.x), w1 * (c[mf][nf][3] + bb.y));
            }
        }
    }
}

// ---------------------------------------------------------------------------
extern "C" void kernel_launch(void* const* d_in, const int* in_sizes, int n_in,
                              void* d_out, int out_size) {
    const float* x  = (const float*)d_in[0];   // [4,2048,1024]
    const float* W  = (const float*)d_in[1];   // [8,1024,1024]
    const float* b  = (const float*)d_in[2];   // [8,1024]
    const float* Wg = (const float*)d_in[3];   // [8,1024]
    const float* bg = (const float*)d_in[4];   // [8]
    float* out = (float*)d_out;                // [4,2048,1024] f32

    static void* cnt_addr = nullptr;
    if (!cnt_addr) {
        cudaGetSymbolAddress(&cnt_addr, g_cnt);
        cudaFuncSetAttribute(moe_gemm_kernel,
                             cudaFuncAttributeMaxDynamicSharedMemorySize, 93184);
    }

    cudaMemsetAsync(cnt_addr, 0, NEXP * sizeof(int));
    fused_prep_gating<<<3072, 256>>>(x, (const float4*)W, Wg, bg, (float4*)out);
    dim3 grid(4, 64, 8);
    moe_gemm_kernel<<<grid, 256, 93184>>>(b, out);
}